// round 1
// baseline (speedup 1.0000x reference)
#include <cuda_runtime.h>
#include <cuda_fp16.h>
#include <cstdint>
#include <cstddef>

#define NB 4096
#define NT 48
#define NI 128
#define NH 512
#define NROWS (NT*NB)   // 196608

// ---------------- static scratch (allocation-free rule) ----------------
__device__ __half g_D16 [(size_t)NROWS*NI];   // D counters as fp16, row = t*NB+b
__device__ __half g_XM16[(size_t)NROWS*NI];   // m*x as fp16
__device__ __half g_WtdT[NI*NH];              // W_td transposed -> [128,512]
__device__ __half g_U16 [NI*NH];              // U_h fp16 [128,512]
__device__ __half g_Wh16[NH*NH];              // W_h fp16 [512,512]
__device__ __half g_G16 [(size_t)NROWS*NH];   // gamma fp16 [T*B,512]
__device__ float  g_Z   [(size_t)NROWS*NH];   // Z fp32 [T*B,512]

// ---------------- PTX helpers ----------------
__device__ __forceinline__ void cp16(uint32_t s, const void* g) {
    asm volatile("cp.async.cg.shared.global [%0], [%1], 16;\n" :: "r"(s), "l"(g));
}
__device__ __forceinline__ void cpcommit() { asm volatile("cp.async.commit_group;\n" ::: "memory"); }

__device__ __forceinline__ void ldm4(uint32_t* d, uint32_t a) {
    asm volatile("ldmatrix.sync.aligned.m8n8.x4.shared.b16 {%0,%1,%2,%3}, [%4];\n"
        : "=r"(d[0]), "=r"(d[1]), "=r"(d[2]), "=r"(d[3]) : "r"(a));
}
__device__ __forceinline__ void ldm4t(uint32_t* d, uint32_t a) {
    asm volatile("ldmatrix.sync.aligned.m8n8.x4.trans.shared.b16 {%0,%1,%2,%3}, [%4];\n"
        : "=r"(d[0]), "=r"(d[1]), "=r"(d[2]), "=r"(d[3]) : "r"(a));
}
__device__ __forceinline__ void mma16816(float* c, const uint32_t* a, uint32_t b0, uint32_t b1) {
    asm volatile("mma.sync.aligned.m16n8k16.row.col.f32.f16.f16.f32 "
        "{%0,%1,%2,%3}, {%4,%5,%6,%7}, {%8,%9}, {%0,%1,%2,%3};\n"
        : "+f"(c[0]), "+f"(c[1]), "+f"(c[2]), "+f"(c[3])
        : "r"(a[0]), "r"(a[1]), "r"(a[2]), "r"(a[3]), "r"(b0), "r"(b1));
}

// ---------------- weight conversion ----------------
__global__ void convert_weights(const float* __restrict__ Wtd, const float* __restrict__ Wh,
                                const float* __restrict__ Uh) {
    int idx = blockIdx.x*blockDim.x + threadIdx.x;
    if (idx < NI*NH) {
        int i = idx / NH, j = idx % NH;
        g_WtdT[idx] = __float2half_rn(Wtd[j*NI + i]);
        g_U16[idx]  = __float2half_rn(Uh[idx]);
    }
    if (idx < NH*NH) g_Wh16[idx] = __float2half_rn(Wh[idx]);
}

// ---------------- D scan + masked x ----------------
__global__ void dscan_kernel(const float* __restrict__ X, const float* __restrict__ M) {
    int idx = blockIdx.x*blockDim.x + threadIdx.x;   // b*128 + i
    int b = idx >> 7, i = idx & 127;
    const float* Xp = X + (size_t)b*NT*NI + i;
    const float* Mp = M + (size_t)b*NT*NI + i;
    size_t o = (size_t)b*NI + i;
    float d = 0.f;
    #pragma unroll 1
    for (int t = 0; t < NT; t++) {
        g_D16[(size_t)t*NB*NI + o] = __float2half_rn(d);
        float m = Mp[(size_t)t*NI];
        float x = Xp[(size_t)t*NI];
        g_XM16[(size_t)t*NB*NI + o] = __float2half_rn(m*x);
        d = 1.f + ((m != 1.f) ? d : 0.f);
    }
}

// ---------------- precompute GEMM: gamma (rows<NROWS half) and Z ----------------
// CTA tile 128x128, K=128 single slab. gridDim.x=4 (N tiles), gridDim.y=2*1536.
__global__ __launch_bounds__(256) void pregemm_kernel(const float* __restrict__ b_td,
                                                      const float* __restrict__ b_h) {
    extern __shared__ __half smem[];
    __half* As = smem;             // 128x128 swizzled
    __half* Bs = smem + 128*128;
    const int tid = threadIdx.x, lane = tid & 31, warp = tid >> 5;
    const int wm = warp & 1, wn = warp >> 1;           // 2x4 warp grid: 64 rows x 32 cols each
    const int n0 = blockIdx.x * 128;
    int mblk = blockIdx.y;
    const bool isZ = mblk >= (NROWS/128);
    if (isZ) mblk -= NROWS/128;
    const int row0 = mblk * 128;
    const __half* A  = isZ ? g_XM16 : g_D16;
    const __half* Bm = isZ ? g_U16  : g_WtdT;
    const float* bias = isZ ? b_h : b_td;

    uint32_t sA = (uint32_t)__cvta_generic_to_shared(As);
    uint32_t sB = (uint32_t)__cvta_generic_to_shared(Bs);

    #pragma unroll
    for (int p = 0; p < 8; p++) {
        int idx = tid + p*256;
        int r = idx >> 4, c = idx & 15;                 // 16 x 16B chunks per row
        cp16(sA + (uint32_t)(r*16 + (c ^ (r & 7)))*16, A  + (size_t)(row0 + r)*NI + c*8);
        cp16(sB + (uint32_t)(r*16 + (c ^ (r & 7)))*16, Bm + (size_t)r*NH + n0 + c*8);
    }
    cpcommit();
    asm volatile("cp.async.wait_group 0;\n" ::: "memory");
    __syncthreads();

    float acc[4][4][4];
    #pragma unroll
    for (int mt = 0; mt < 4; mt++)
        #pragma unroll
        for (int nt = 0; nt < 4; nt++)
            #pragma unroll
            for (int q = 0; q < 4; q++) acc[mt][nt][q] = 0.f;

    #pragma unroll
    for (int kk = 0; kk < 8; kk++) {
        uint32_t a[4][4];
        #pragma unroll
        for (int mt = 0; mt < 4; mt++) {
            int r = wm*64 + mt*16 + (lane & 15);
            int c = kk*2 + (lane >> 4);
            ldm4(a[mt], sA + (uint32_t)(r*16 + (c ^ (r & 7)))*16);
        }
        uint32_t bf[2][4];
        #pragma unroll
        for (int n2 = 0; n2 < 2; n2++) {
            int g = lane >> 3;
            int r = kk*16 + (g & 1)*8 + (lane & 7);
            int c = wn*4 + n2*2 + (g >> 1);
            ldm4t(bf[n2], sB + (uint32_t)(r*16 + (c ^ (r & 7)))*16);
        }
        #pragma unroll
        for (int mt = 0; mt < 4; mt++)
            #pragma unroll
            for (int nt = 0; nt < 4; nt++)
                mma16816(acc[mt][nt], a[mt], bf[nt>>1][(nt&1)*2], bf[nt>>1][(nt&1)*2+1]);
    }

    #pragma unroll
    for (int mt = 0; mt < 4; mt++) {
        #pragma unroll
        for (int nt = 0; nt < 4; nt++) {
            int col = n0 + wn*32 + nt*8 + (lane & 3)*2;
            float bv0 = bias[col], bv1 = bias[col+1];
            #pragma unroll
            for (int hh = 0; hh < 2; hh++) {
                int r = row0 + wm*64 + mt*16 + (lane >> 2) + hh*8;
                float v0 = acc[mt][nt][hh*2+0] + bv0;
                float v1 = acc[mt][nt][hh*2+1] + bv1;
                if (!isZ) {
                    v0 = __expf(-fmaxf(v0, 0.f));
                    v1 = __expf(-fmaxf(v1, 0.f));
                    *reinterpret_cast<__half2*>(&g_G16[(size_t)r*NH + col]) = __floats2half2_rn(v0, v1);
                } else {
                    *reinterpret_cast<float2*>(&g_Z[(size_t)r*NH + col]) = make_float2(v0, v1);
                }
            }
        }
    }
}

// ---------------- recurrent kernel ----------------
// 128 CTAs x 32 batch rows, 8 warps (each owns 64 output cols). hpre fp16 in smem,
// W_h streamed in 8 double-buffered 64x512 fp16 slabs via cp.async.
__global__ __launch_bounds__(256) void rec_kernel(float* __restrict__ out) {
    extern __shared__ __half smem[];
    __half* Hs = smem;                         // 32x512 swizzled hpre
    uint32_t sH  = (uint32_t)__cvta_generic_to_shared(Hs);
    uint32_t sW0 = (uint32_t)__cvta_generic_to_shared(smem + 32*512);
    uint32_t sW1 = (uint32_t)__cvta_generic_to_shared(smem + 32*512 + 64*512);

    const int tid = threadIdx.x, lane = tid & 31, warp = tid >> 5;
    const int b0 = blockIdx.x * 32;
    const int rA = lane >> 2;
    const int cA = (lane & 3)*2;

    // zero hpre (h_0 * gamma_0 == 0 since h starts at 0)
    #pragma unroll
    for (int p = 0; p < 32; p++)
        reinterpret_cast<uint32_t*>(Hs)[tid + p*256] = 0u;

    #pragma unroll 1
    for (int t = 0; t < NT; t++) {
        // issue W slab 0 (independent of hpre)
        {
            const __half* src = g_Wh16;
            #pragma unroll
            for (int p = 0; p < 16; p++) {
                int idx = tid + p*256;
                int r = idx >> 6, c = idx & 63;           // 64 rows x 64 chunks
                cp16(sW0 + (uint32_t)(r*64 + (c ^ (r & 7)))*16, src + (size_t)r*NH + c*8);
            }
            cpcommit();
        }

        float acc[2][8][4];
        #pragma unroll
        for (int mt = 0; mt < 2; mt++)
            #pragma unroll
            for (int nt = 0; nt < 8; nt++)
                #pragma unroll
                for (int q = 0; q < 4; q++) acc[mt][nt][q] = 0.f;

        #pragma unroll
        for (int s = 0; s < 8; s++) {
            uint32_t sCur = (s & 1) ? sW1 : sW0;
            if (s < 7) {
                uint32_t sNext = (s & 1) ? sW0 : sW1;
                const __half* src = g_Wh16 + (size_t)(s + 1)*64*NH;
                #pragma unroll
                for (int p = 0; p < 16; p++) {
                    int idx = tid + p*256;
                    int r = idx >> 6, c = idx & 63;
                    cp16(sNext + (uint32_t)(r*64 + (c ^ (r & 7)))*16, src + (size_t)r*NH + c*8);
                }
                cpcommit();
                asm volatile("cp.async.wait_group 1;\n" ::: "memory");
            } else {
                asm volatile("cp.async.wait_group 0;\n" ::: "memory");
            }
            __syncthreads();   // slab s visible (also orders hpre writes before first read)

            #pragma unroll
            for (int kk = 0; kk < 4; kk++) {
                uint32_t a[2][4];
                #pragma unroll
                for (int mt = 0; mt < 2; mt++) {
                    int r = mt*16 + (lane & 15);
                    int c = s*8 + kk*2 + (lane >> 4);
                    ldm4(a[mt], sH + (uint32_t)(r*64 + (c ^ (r & 7)))*16);
                }
                uint32_t bf[4][4];
                #pragma unroll
                for (int n2 = 0; n2 < 4; n2++) {
                    int g = lane >> 3;
                    int r = kk*16 + (g & 1)*8 + (lane & 7);
                    int c = warp*8 + n2*2 + (g >> 1);
                    ldm4t(bf[n2], sCur + (uint32_t)(r*64 + (c ^ (r & 7)))*16);
                }
                #pragma unroll
                for (int mt = 0; mt < 2; mt++)
                    #pragma unroll
                    for (int nt = 0; nt < 8; nt++)
                        mma16816(acc[mt][nt], a[mt], bf[nt>>1][(nt&1)*2], bf[nt>>1][(nt&1)*2+1]);
            }
            __syncthreads();   // all warps done with buffer before re-issue
        }

        // epilogue: h = sigmoid(acc + Z); write output; write hpre_{t+1} = fp16(h * gamma_{t+1})
        size_t zrow = (size_t)t*NB + b0;
        #pragma unroll
        for (int mt = 0; mt < 2; mt++) {
            #pragma unroll
            for (int nt = 0; nt < 8; nt++) {
                int col = warp*64 + nt*8 + cA;
                #pragma unroll
                for (int hh = 0; hh < 2; hh++) {
                    int r = mt*16 + rA + hh*8;
                    float2 z = *reinterpret_cast<const float2*>(&g_Z[(zrow + r)*NH + col]);
                    float s0 = acc[mt][nt][hh*2+0] + z.x;
                    float s1 = acc[mt][nt][hh*2+1] + z.y;
                    float h0 = 1.f/(1.f + __expf(-s0));
                    float h1 = 1.f/(1.f + __expf(-s1));
                    *reinterpret_cast<float2*>(&out[(((size_t)(b0 + r))*NT + t)*NH + col]) =
                        make_float2(h0, h1);
                    if (t + 1 < NT) {
                        __half2 gm = *reinterpret_cast<const __half2*>(
                            &g_G16[(zrow + (size_t)NB + r)*NH + col]);
                        float2 gf = __half22float2(gm);
                        __half2 hp = __floats2half2_rn(h0*gf.x, h1*gf.y);
                        int ch = col >> 3;
                        char* p = reinterpret_cast<char*>(Hs)
                                + (r*64 + (ch ^ (r & 7)))*16 + (col & 7)*2;
                        *reinterpret_cast<__half2*>(p) = hp;
                    }
                }
            }
        }
        // next iteration's first __syncthreads orders these hpre writes before reads
    }
}

// ---------------- launch ----------------
extern "C" void kernel_launch(void* const* d_in, const int* in_sizes, int n_in,
                              void* d_out, int out_size) {
    const float* X   = (const float*)d_in[0];
    const float* M   = (const float*)d_in[1];
    const float* Wtd = (const float*)d_in[2];
    const float* btd = (const float*)d_in[3];
    // d_in[4] = W_hr, d_in[5] = b_hr : provably dead (m binary => x_c*m == m*x)
    const float* Wh  = (const float*)d_in[6];
    const float* Uh  = (const float*)d_in[7];
    const float* bh  = (const float*)d_in[8];
    float* out = (float*)d_out;

    cudaFuncSetAttribute(pregemm_kernel, cudaFuncAttributeMaxDynamicSharedMemorySize, 65536);
    cudaFuncSetAttribute(rec_kernel,     cudaFuncAttributeMaxDynamicSharedMemorySize, 163840);

    convert_weights<<<1024, 256>>>(Wtd, Wh, Uh);
    dscan_kernel<<<(NB*NI)/256, 256>>>(X, M);
    pregemm_kernel<<<dim3(4, 2*(NROWS/128)), 256, 65536>>>(btd, bh);
    rec_kernel<<<NB/32, 256, 163840>>>(out);
}

// round 2
// speedup vs baseline: 1.3940x; 1.3940x over previous
#include <cuda_runtime.h>
#include <cuda_fp16.h>
#include <cstdint>
#include <cstddef>

#define NB 4096
#define NT 48
#define NI 128
#define NH 512
#define NROWS (NT*NB)   // 196608

// ---------------- static scratch (allocation-free rule) ----------------
__device__ __half g_D16 [(size_t)NROWS*NI];   // D counters as fp16, row = t*NB+b
__device__ __half g_XM16[(size_t)NROWS*NI];   // m*x as fp16
__device__ __half g_WtdT[NI*NH];              // W_td transposed -> [128,512]
__device__ __half g_U16 [NI*NH];              // U_h fp16 [128,512]
__device__ __half g_Wh16[NH*NH];              // W_h fp16 [512,512]
__device__ __half g_G16 [(size_t)NROWS*NH];   // gamma fp16 [T*B,512]
__device__ float  g_Z   [(size_t)NROWS*NH];   // Z fp32 [T*B,512]

// ---------------- PTX helpers ----------------
__device__ __forceinline__ void cp16(uint32_t s, const void* g) {
    asm volatile("cp.async.cg.shared.global [%0], [%1], 16;\n" :: "r"(s), "l"(g));
}
__device__ __forceinline__ void cpcommit() { asm volatile("cp.async.commit_group;\n" ::: "memory"); }

__device__ __forceinline__ void ldm4(uint32_t* d, uint32_t a) {
    asm volatile("ldmatrix.sync.aligned.m8n8.x4.shared.b16 {%0,%1,%2,%3}, [%4];\n"
        : "=r"(d[0]), "=r"(d[1]), "=r"(d[2]), "=r"(d[3]) : "r"(a));
}
__device__ __forceinline__ void ldm4t(uint32_t* d, uint32_t a) {
    asm volatile("ldmatrix.sync.aligned.m8n8.x4.trans.shared.b16 {%0,%1,%2,%3}, [%4];\n"
        : "=r"(d[0]), "=r"(d[1]), "=r"(d[2]), "=r"(d[3]) : "r"(a));
}
__device__ __forceinline__ void mma16816(float* c, const uint32_t* a, uint32_t b0, uint32_t b1) {
    asm volatile("mma.sync.aligned.m16n8k16.row.col.f32.f16.f16.f32 "
        "{%0,%1,%2,%3}, {%4,%5,%6,%7}, {%8,%9}, {%0,%1,%2,%3};\n"
        : "+f"(c[0]), "+f"(c[1]), "+f"(c[2]), "+f"(c[3])
        : "r"(a[0]), "r"(a[1]), "r"(a[2]), "r"(a[3]), "r"(b0), "r"(b1));
}

// ---------------- weight conversion ----------------
__global__ void convert_weights(const float* __restrict__ Wtd, const float* __restrict__ Wh,
                                const float* __restrict__ Uh) {
    int idx = blockIdx.x*blockDim.x + threadIdx.x;
    if (idx < NI*NH) {
        int i = idx / NH, j = idx % NH;
        g_WtdT[idx] = __float2half_rn(Wtd[j*NI + i]);
        g_U16[idx]  = __float2half_rn(Uh[idx]);
    }
    if (idx < NH*NH) g_Wh16[idx] = __float2half_rn(Wh[idx]);
}

// ---------------- D scan + masked x ----------------
__global__ void dscan_kernel(const float* __restrict__ X, const float* __restrict__ M) {
    int idx = blockIdx.x*blockDim.x + threadIdx.x;   // b*128 + i
    int b = idx >> 7, i = idx & 127;
    const float* Xp = X + (size_t)b*NT*NI + i;
    const float* Mp = M + (size_t)b*NT*NI + i;
    size_t o = (size_t)b*NI + i;
    float d = 0.f;
    #pragma unroll 1
    for (int t = 0; t < NT; t++) {
        g_D16[(size_t)t*NB*NI + o] = __float2half_rn(d);
        float m = Mp[(size_t)t*NI];
        float x = Xp[(size_t)t*NI];
        g_XM16[(size_t)t*NB*NI + o] = __float2half_rn(m*x);
        d = 1.f + ((m != 1.f) ? d : 0.f);
    }
}

// ---------------- precompute GEMM: gamma (rows<NROWS half) and Z ----------------
// CTA tile 128x128, K=128 single slab. gridDim.x=4 (N tiles), gridDim.y=2*1536.
__global__ __launch_bounds__(256) void pregemm_kernel(const float* __restrict__ b_td,
                                                      const float* __restrict__ b_h) {
    extern __shared__ __half smem[];
    __half* As = smem;             // 128x128 swizzled
    __half* Bs = smem + 128*128;
    const int tid = threadIdx.x, lane = tid & 31, warp = tid >> 5;
    const int wm = warp & 1, wn = warp >> 1;           // 2x4 warp grid: 64 rows x 32 cols each
    const int n0 = blockIdx.x * 128;
    int mblk = blockIdx.y;
    const bool isZ = mblk >= (NROWS/128);
    if (isZ) mblk -= NROWS/128;
    const int row0 = mblk * 128;
    const __half* A  = isZ ? g_XM16 : g_D16;
    const __half* Bm = isZ ? g_U16  : g_WtdT;
    const float* bias = isZ ? b_h : b_td;

    uint32_t sA = (uint32_t)__cvta_generic_to_shared(As);
    uint32_t sB = (uint32_t)__cvta_generic_to_shared(Bs);

    #pragma unroll
    for (int p = 0; p < 8; p++) {
        int idx = tid + p*256;
        int r = idx >> 4, c = idx & 15;                 // 16 x 16B chunks per row
        cp16(sA + (uint32_t)(r*16 + (c ^ (r & 7)))*16, A  + (size_t)(row0 + r)*NI + c*8);
        cp16(sB + (uint32_t)(r*16 + (c ^ (r & 7)))*16, Bm + (size_t)r*NH + n0 + c*8);
    }
    cpcommit();
    asm volatile("cp.async.wait_group 0;\n" ::: "memory");
    __syncthreads();

    float acc[4][4][4];
    #pragma unroll
    for (int mt = 0; mt < 4; mt++)
        #pragma unroll
        for (int nt = 0; nt < 4; nt++)
            #pragma unroll
            for (int q = 0; q < 4; q++) acc[mt][nt][q] = 0.f;

    #pragma unroll
    for (int kk = 0; kk < 8; kk++) {
        uint32_t a[4][4];
        #pragma unroll
        for (int mt = 0; mt < 4; mt++) {
            int r = wm*64 + mt*16 + (lane & 15);
            int c = kk*2 + (lane >> 4);
            ldm4(a[mt], sA + (uint32_t)(r*16 + (c ^ (r & 7)))*16);
        }
        uint32_t bf[2][4];
        #pragma unroll
        for (int n2 = 0; n2 < 2; n2++) {
            int g = lane >> 3;
            int r = kk*16 + (g & 1)*8 + (lane & 7);
            int c = wn*4 + n2*2 + (g >> 1);
            ldm4t(bf[n2], sB + (uint32_t)(r*16 + (c ^ (r & 7)))*16);
        }
        #pragma unroll
        for (int mt = 0; mt < 4; mt++)
            #pragma unroll
            for (int nt = 0; nt < 4; nt++)
                mma16816(acc[mt][nt], a[mt], bf[nt>>1][(nt&1)*2], bf[nt>>1][(nt&1)*2+1]);
    }

    #pragma unroll
    for (int mt = 0; mt < 4; mt++) {
        #pragma unroll
        for (int nt = 0; nt < 4; nt++) {
            int col = n0 + wn*32 + nt*8 + (lane & 3)*2;
            float bv0 = bias[col], bv1 = bias[col+1];
            #pragma unroll
            for (int hh = 0; hh < 2; hh++) {
                int r = row0 + wm*64 + mt*16 + (lane >> 2) + hh*8;
                float v0 = acc[mt][nt][hh*2+0] + bv0;
                float v1 = acc[mt][nt][hh*2+1] + bv1;
                if (!isZ) {
                    v0 = __expf(-fmaxf(v0, 0.f));
                    v1 = __expf(-fmaxf(v1, 0.f));
                    *reinterpret_cast<__half2*>(&g_G16[(size_t)r*NH + col]) = __floats2half2_rn(v0, v1);
                } else {
                    *reinterpret_cast<float2*>(&g_Z[(size_t)r*NH + col]) = make_float2(v0, v1);
                }
            }
        }
    }
}

// ---------------- recurrent kernel ----------------
// 128 CTAs x 32 batch rows, 8 warps (each owns 64 output cols). hpre fp16 in smem,
// W_h streamed in 8 double-buffered 64x512 fp16 slabs via cp.async.
__global__ __launch_bounds__(256) void rec_kernel(float* __restrict__ out) {
    extern __shared__ __half smem[];
    __half* Hs = smem;                         // 32x512 swizzled hpre
    uint32_t sH  = (uint32_t)__cvta_generic_to_shared(Hs);
    uint32_t sW0 = (uint32_t)__cvta_generic_to_shared(smem + 32*512);
    uint32_t sW1 = (uint32_t)__cvta_generic_to_shared(smem + 32*512 + 64*512);

    const int tid = threadIdx.x, lane = tid & 31, warp = tid >> 5;
    const int b0 = blockIdx.x * 32;
    const int rA = lane >> 2;
    const int cA = (lane & 3)*2;

    // zero hpre (h_0 * gamma_0 == 0 since h starts at 0)
    #pragma unroll
    for (int p = 0; p < 32; p++)
        reinterpret_cast<uint32_t*>(Hs)[tid + p*256] = 0u;

    #pragma unroll 1
    for (int t = 0; t < NT; t++) {
        // issue W slab 0 (independent of hpre)
        {
            const __half* src = g_Wh16;
            #pragma unroll
            for (int p = 0; p < 16; p++) {
                int idx = tid + p*256;
                int r = idx >> 6, c = idx & 63;           // 64 rows x 64 chunks
                cp16(sW0 + (uint32_t)(r*64 + (c ^ (r & 7)))*16, src + (size_t)r*NH + c*8);
            }
            cpcommit();
        }

        float acc[2][8][4];
        #pragma unroll
        for (int mt = 0; mt < 2; mt++)
            #pragma unroll
            for (int nt = 0; nt < 8; nt++)
                #pragma unroll
                for (int q = 0; q < 4; q++) acc[mt][nt][q] = 0.f;

        #pragma unroll
        for (int s = 0; s < 8; s++) {
            uint32_t sCur = (s & 1) ? sW1 : sW0;
            if (s < 7) {
                uint32_t sNext = (s & 1) ? sW0 : sW1;
                const __half* src = g_Wh16 + (size_t)(s + 1)*64*NH;
                #pragma unroll
                for (int p = 0; p < 16; p++) {
                    int idx = tid + p*256;
                    int r = idx >> 6, c = idx & 63;
                    cp16(sNext + (uint32_t)(r*64 + (c ^ (r & 7)))*16, src + (size_t)r*NH + c*8);
                }
                cpcommit();
                asm volatile("cp.async.wait_group 1;\n" ::: "memory");
            } else {
                asm volatile("cp.async.wait_group 0;\n" ::: "memory");
            }
            __syncthreads();   // slab s visible (also orders hpre writes before first read)

            #pragma unroll
            for (int kk = 0; kk < 4; kk++) {
                uint32_t a[2][4];
                #pragma unroll
                for (int mt = 0; mt < 2; mt++) {
                    int r = mt*16 + (lane & 15);
                    int c = s*8 + kk*2 + (lane >> 4);
                    ldm4(a[mt], sH + (uint32_t)(r*64 + (c ^ (r & 7)))*16);
                }
                uint32_t bf[4][4];
                #pragma unroll
                for (int n2 = 0; n2 < 4; n2++) {
                    int g = lane >> 3;
                    int r = kk*16 + (g & 1)*8 + (lane & 7);
                    int c = warp*8 + n2*2 + (g >> 1);
                    ldm4t(bf[n2], sCur + (uint32_t)(r*64 + (c ^ (r & 7)))*16);
                }
                #pragma unroll
                for (int mt = 0; mt < 2; mt++)
                    #pragma unroll
                    for (int nt = 0; nt < 8; nt++)
                        mma16816(acc[mt][nt], a[mt], bf[nt>>1][(nt&1)*2], bf[nt>>1][(nt&1)*2+1]);
            }
            __syncthreads();   // all warps done with buffer before re-issue
        }

        // epilogue: h = sigmoid(acc + Z); write output; write hpre_{t+1} = fp16(h * gamma_{t+1})
        size_t zrow = (size_t)t*NB + b0;
        #pragma unroll
        for (int mt = 0; mt < 2; mt++) {
            #pragma unroll
            for (int nt = 0; nt < 8; nt++) {
                int col = warp*64 + nt*8 + cA;
                #pragma unroll
                for (int hh = 0; hh < 2; hh++) {
                    int r = mt*16 + rA + hh*8;
                    float2 z = *reinterpret_cast<const float2*>(&g_Z[(zrow + r)*NH + col]);
                    float s0 = acc[mt][nt][hh*2+0] + z.x;
                    float s1 = acc[mt][nt][hh*2+1] + z.y;
                    float h0 = 1.f/(1.f + __expf(-s0));
                    float h1 = 1.f/(1.f + __expf(-s1));
                    *reinterpret_cast<float2*>(&out[(((size_t)(b0 + r))*NT + t)*NH + col]) =
                        make_float2(h0, h1);
                    if (t + 1 < NT) {
                        __half2 gm = *reinterpret_cast<const __half2*>(
                            &g_G16[(zrow + (size_t)NB + r)*NH + col]);
                        float2 gf = __half22float2(gm);
                        __half2 hp = __floats2half2_rn(h0*gf.x, h1*gf.y);
                        int ch = col >> 3;
                        char* p = reinterpret_cast<char*>(Hs)
                                + (r*64 + (ch ^ (r & 7)))*16 + (col & 7)*2;
                        *reinterpret_cast<__half2*>(p) = hp;
                    }
                }
            }
        }
        // next iteration's first __syncthreads orders these hpre writes before reads
    }
}

// ---------------- launch ----------------
extern "C" void kernel_launch(void* const* d_in, const int* in_sizes, int n_in,
                              void* d_out, int out_size) {
    const float* X   = (const float*)d_in[0];
    const float* M   = (const float*)d_in[1];
    const float* Wtd = (const float*)d_in[2];
    const float* btd = (const float*)d_in[3];
    // d_in[4] = W_hr, d_in[5] = b_hr : provably dead (m binary => x_c*m == m*x)
    const float* Wh  = (const float*)d_in[6];
    const float* Uh  = (const float*)d_in[7];
    const float* bh  = (const float*)d_in[8];
    float* out = (float*)d_out;

    cudaFuncSetAttribute(pregemm_kernel, cudaFuncAttributeMaxDynamicSharedMemorySize, 65536);
    cudaFuncSetAttribute(rec_kernel,     cudaFuncAttributeMaxDynamicSharedMemorySize, 163840);

    convert_weights<<<1024, 256>>>(Wtd, Wh, Uh);
    dscan_kernel<<<(NB*NI)/256, 256>>>(X, M);
    pregemm_kernel<<<dim3(4, 2*(NROWS/128)), 256, 65536>>>(btd, bh);
    rec_kernel<<<NB/32, 256, 163840>>>(out);
}